// round 14
// baseline (speedup 1.0000x reference)
#include <cuda_runtime.h>
#include <cstdint>
#include <math.h>

#ifndef M_PI
#define M_PI 3.14159265358979323846
#endif

#define NN 10000
#define EE 160000
#define FF 128
#define RR 20
#define F3 (3*FF)
#define CUT_D 3.0f
#define LL 3

// packed split-weight layout, uints per layer
#define PSu  90112
#define OW1u 0          /* w1T  [128][64u]  */
#define OW2u 8192       /* w2T  [384][64u]  */
#define OUVu 32768      /* UVwT [256][64u]  */
#define OU1u 49152      /* u1T  [128][128u] */
#define OU2u 65536      /* u2T  [384][64u]  */

// ---------------- scratch (device globals; no allocation allowed) ----------
__device__ float g_rbfc[EE*RR];
__device__ float g_cut[EE];
__device__ float g_dir[EE*3];
__device__ int   g_inside[EE];
__device__ int   g_deg[NN];
__device__ int   g_rowptr[NN+1];
__device__ int   g_fill[NN];
__device__ int   g_csr[EE];
__device__ float g_sA[NN*FF], g_sB[NN*FF];
__device__ float g_vA[NN*3*FF], g_vB[NN*3*FF];   // stored [N,3,F]
__device__ float g_phi[NN*F3];
__device__ float g_UVv[NN*3*2*FF];               // [3N][256]: Uv | Vv
__device__ float g_a[NN*F3];
// split bf16 hi/lo packed operands (uint = bf16x2, even elem in low half)
__device__ __align__(16) uint32_t g_wH[LL*PSu],  g_wL[LL*PSu];
__device__ __align__(16) uint32_t g_sH[NN*64],   g_sL[NN*64];
__device__ __align__(16) uint32_t g_hidH[NN*64], g_hidL[NN*64];
__device__ __align__(16) uint32_t g_vH[NN*192],  g_vL[NN*192];   // [3N][64u]
__device__ __align__(16) uint32_t g_xH[NN*128],  g_xL[NN*128];   // [N][128u]

// ---------------- bf16 split helpers ----------------------------------------
__device__ __forceinline__ uint32_t bf16bits_hi(float x) {
    uint32_t u = __float_as_uint(x);
    return (u + 0x7FFFu + ((u >> 16) & 1u)) & 0xFFFF0000u;   // float bits of rn(bf16)
}
__device__ __forceinline__ void split2(float x, float y, uint32_t& hi2, uint32_t& lo2) {
    uint32_t hx = bf16bits_hi(x);
    uint32_t hy = bf16bits_hi(y);
    float lx = x - __uint_as_float(hx);
    float ly = y - __uint_as_float(hy);
    hi2 = (hx >> 16) | hy;
    lo2 = (bf16bits_hi(lx) >> 16) | bf16bits_hi(ly);
}
__device__ __forceinline__ float silu_fast(float x) {
    return __fdividef(x, 1.0f + __expf(-x));
}

__device__ __forceinline__ uint32_t smem_u32(const void* p) {
    uint32_t a;
    asm("{ .reg .u64 t; cvta.to.shared.u64 t, %1; cvt.u32.u64 %0, t; }"
        : "=r"(a) : "l"(p));
    return a;
}
__device__ __forceinline__ void cp_async16(uint32_t dst, const void* src, int srcBytes) {
    asm volatile("cp.async.cg.shared.global [%0], [%1], 16, %2;"
                 :: "r"(dst), "l"(src), "r"(srcBytes) : "memory");
}
__device__ __forceinline__ void cp_commit() {
    asm volatile("cp.async.commit_group;" ::: "memory");
}
// m16n8k16 bf16 MMA: a = {a0,a1,a2,a3}, b = {b0,b1}
__device__ __forceinline__ void mma_bf16_k16(float* c, const uint32_t* a, const uint32_t* b) {
    asm volatile(
        "mma.sync.aligned.m16n8k16.row.col.f32.bf16.bf16.f32 "
        "{%0,%1,%2,%3}, {%4,%5,%6,%7}, {%8,%9}, {%0,%1,%2,%3};"
        : "+f"(c[0]), "+f"(c[1]), "+f"(c[2]), "+f"(c[3])
        : "r"(a[0]), "r"(a[1]), "r"(a[2]), "r"(a[3]), "r"(b[0]), "r"(b[1]));
}

// ================= bf16x3 mma.sync GEMM (k16, 256x64 tile, 2-stage) =========
// C[M,N] = act(A[M,K] @ BT[N,K]^T + bias). N mult of 64, K mult of 32.
// A,B packed split bf16. Out: fp32 (Cf) or split (CH/CL).
#define GBM 256
#define GBN 64
#define USTR 20
#define ATS (256*USTR)          /* 5120u per A matrix (hi or lo) */
#define BTS (64*USTR)           /* 1280u per B matrix */
#define STGU (2*ATS + 2*BTS)    /* 12800u = 50 KB per stage */
#define NSTG 2
#define GSMEM_BYTES (NSTG*STGU*4)   /* 102400 B dynamic */

__global__ __launch_bounds__(256) void gemm_bf16_kernel(
    const uint32_t* __restrict__ AH, const uint32_t* __restrict__ AL,
    const uint32_t* __restrict__ BH, const uint32_t* __restrict__ BL,
    const float* __restrict__ bias, float* __restrict__ Cf,
    uint32_t* __restrict__ CH, uint32_t* __restrict__ CL,
    int M, int K, int N, int act)
{
    extern __shared__ __align__(16) uint32_t sm[];
    uint32_t sb = smem_u32(sm);
    int tid  = threadIdx.x;
    int lane = tid & 31;
    int warp = tid >> 5;
    int wm = warp & 1;                  // 2 warps along M (128 rows each)
    int wn = warp >> 1;                 // 4 warps along N (16 cols each)
    int g  = lane >> 2;
    int t  = lane & 3;
    int rowBase = blockIdx.y * GBM;
    int colBase = blockIdx.x * GBN;
    int K2 = K >> 1;

    int lrow = tid >> 2;                // 0..63
    int lq   = tid & 3;                 // float4 slot (4 uints)

    float acc[8][2][4];
    #pragma unroll
    for (int mt = 0; mt < 8; mt++)
        #pragma unroll
        for (int nt = 0; nt < 2; nt++)
            #pragma unroll
            for (int q = 0; q < 4; q++) acc[mt][nt][q] = 0.0f;

    int chunks = K >> 5;

    auto loadChunk = [&](int c) {
        if (c < chunks) {
            int s = c & (NSTG - 1);
            int k0u = c << 4;
            uint32_t base = sb + (uint32_t)(s * STGU) * 4u;
            // A: rows lrow, +64, +128, +192, hi+lo
            #pragma unroll
            for (int it = 0; it < 4; it++) {
                int r = lrow + it * 64;
                int gr = rowBase + r;
                int ok = (gr < M);
                size_t off = (size_t)(ok ? gr : 0) * K2 + k0u + lq * 4;
                uint32_t dr = base + (uint32_t)(r * USTR + lq * 4) * 4u;
                cp_async16(dr, &AH[off], ok ? 16 : 0);
                cp_async16(dr + (uint32_t)ATS * 4u, &AL[off], ok ? 16 : 0);
            }
            // B: row lrow, hi+lo
            size_t boff = (size_t)(colBase + lrow) * K2 + k0u + lq * 4;
            uint32_t db = base + (uint32_t)(2*ATS + lrow * USTR + lq * 4) * 4u;
            cp_async16(db, &BH[boff], 16);
            cp_async16(db + (uint32_t)BTS * 4u, &BL[boff], 16);
        }
        cp_commit();
    };

    loadChunk(0);
    loadChunk(1);

    for (int c = 0; c < chunks; c++) {
        asm volatile("cp.async.wait_group 1;" ::: "memory");
        __syncthreads();

        const uint32_t* st = sm + (c & (NSTG - 1)) * STGU;
        #pragma unroll
        for (int ks = 0; ks < 2; ks++) {                 // two k16 steps per chunk
            uint32_t bHf[2][2], bLf[2][2];
            #pragma unroll
            for (int nt = 0; nt < 2; nt++) {
                int uo = 2*ATS + (wn*16 + nt*8 + g) * USTR + ks*8 + t;
                bHf[nt][0] = st[uo];
                bHf[nt][1] = st[uo + 4];
                bLf[nt][0] = st[BTS + uo];
                bLf[nt][1] = st[BTS + uo + 4];
            }
            #pragma unroll
            for (int mt = 0; mt < 8; mt++) {
                uint32_t aHf[4], aLf[4];
                int uo = (wm*128 + mt*16 + g) * USTR + ks*8 + t;
                aHf[0] = st[uo];
                aHf[1] = st[uo + 8*USTR];
                aHf[2] = st[uo + 4];
                aHf[3] = st[uo + 4 + 8*USTR];
                aLf[0] = st[ATS + uo];
                aLf[1] = st[ATS + uo + 8*USTR];
                aLf[2] = st[ATS + uo + 4];
                aLf[3] = st[ATS + uo + 4 + 8*USTR];
                #pragma unroll
                for (int nt = 0; nt < 2; nt++) {
                    mma_bf16_k16(acc[mt][nt], aHf, bHf[nt]);
                    mma_bf16_k16(acc[mt][nt], aHf, bLf[nt]);
                    mma_bf16_k16(acc[mt][nt], aLf, bHf[nt]);
                }
            }
        }
        __syncthreads();
        loadChunk(c + 2);
    }

    // ---- epilogue ----
    int N2 = N >> 1;
    #pragma unroll
    for (int mt = 0; mt < 8; mt++) {
        int r0 = rowBase + wm*128 + mt*16 + g;
        int r1 = r0 + 8;
        #pragma unroll
        for (int nt = 0; nt < 2; nt++) {
            int cc = colBase + wn*16 + nt*8 + t*2;
            float b0 = 0.f, b1 = 0.f;
            if (bias) { b0 = bias[cc]; b1 = bias[cc+1]; }
            float o0 = acc[mt][nt][0] + b0;
            float o1 = acc[mt][nt][1] + b1;
            float o2 = acc[mt][nt][2] + b0;
            float o3 = acc[mt][nt][3] + b1;
            if (act == 1) {
                o0 = silu_fast(o0);
                o1 = silu_fast(o1);
                o2 = silu_fast(o2);
                o3 = silu_fast(o3);
            }
            if (CH) {
                uint32_t h, l;
                if (r0 < M) {
                    split2(o0, o1, h, l);
                    CH[(size_t)r0*N2 + (cc>>1)] = h;
                    CL[(size_t)r0*N2 + (cc>>1)] = l;
                }
                if (r1 < M) {
                    split2(o2, o3, h, l);
                    CH[(size_t)r1*N2 + (cc>>1)] = h;
                    CL[(size_t)r1*N2 + (cc>>1)] = l;
                }
            } else {
                if (r0 < M) *(float2*)&Cf[(size_t)r0*N + cc] = make_float2(o0, o1);
                if (r1 < M) *(float2*)&Cf[(size_t)r1*N + cc] = make_float2(o2, o3);
            }
        }
    }
}

// ================= graph-structure + elementwise kernels =====================
__global__ void zero_counts_kernel() {
    int i = blockIdx.x * blockDim.x + threadIdx.x;
    if (i < NN) { g_deg[i] = 0; g_fill[i] = 0; }
}

__global__ void edge_pre_kernel(const float* __restrict__ pos,
                                const int* __restrict__ idx_i,
                                const int* __restrict__ idx_j) {
    int e = blockIdx.x * blockDim.x + threadIdx.x;
    if (e >= EE) return;
    int i = idx_i[e], j = idx_j[e];
    float rx = pos[j*3+0] - pos[i*3+0];
    float ry = pos[j*3+1] - pos[i*3+1];
    float rz = pos[j*3+2] - pos[i*3+2];
    float sq = rx*rx + ry*ry + rz*rz;
    float d  = sqrtf(sq);
    float inv = 1.0f / d;
    g_dir[e*3+0] = rx*inv;
    g_dir[e*3+1] = ry*inv;
    g_dir[e*3+2] = rz*inv;
    int ins = (d < CUT_D) ? 1 : 0;
    float base = (float)M_PI * d / CUT_D;
    float s1, c1;
    sincosf(base, &s1, &c1);
    float cut = ins ? 0.5f * (c1 + 1.0f) : 0.0f;
    g_cut[e] = cut;
    g_inside[e] = ins;
    float ic = inv * cut;
    float twoc = 2.0f * c1;
    float sk = s1, skm1 = 0.0f;
    #pragma unroll
    for (int k = 0; k < RR; k++) {
        g_rbfc[e*RR+k] = sk * ic;
        float nxt = twoc * sk - skm1;
        skm1 = sk; sk = nxt;
    }
    if (ins) atomicAdd(&g_deg[i], 1);
}

// warp-shuffle single-block scan (1024 threads, 32 warps)
__global__ void scan_kernel() {
    __shared__ int wsum[32];
    __shared__ int carry;
    int tid = threadIdx.x, lane = tid & 31, wid = tid >> 5;
    if (tid == 0) { carry = 0; g_rowptr[0] = 0; }
    __syncthreads();
    for (int base = 0; base < NN; base += 1024) {
        int i = base + tid;
        int x = (i < NN) ? g_deg[i] : 0;
        #pragma unroll
        for (int off = 1; off < 32; off <<= 1) {
            int y = __shfl_up_sync(0xFFFFFFFFu, x, off);
            if (lane >= off) x += y;
        }
        if (lane == 31) wsum[wid] = x;
        __syncthreads();
        if (wid == 0) {
            int s = wsum[lane];
            #pragma unroll
            for (int off = 1; off < 32; off <<= 1) {
                int y = __shfl_up_sync(0xFFFFFFFFu, s, off);
                if (lane >= off) s += y;
            }
            wsum[lane] = s;
        }
        __syncthreads();
        int pre = (wid > 0) ? wsum[wid - 1] : 0;
        int inc = x + pre + carry;
        if (i < NN) g_rowptr[i + 1] = inc;
        __syncthreads();
        if (tid == 1023) carry = inc;
        __syncthreads();
    }
}

__global__ void scatter_kernel(const int* __restrict__ idx_i) {
    int e = blockIdx.x * blockDim.x + threadIdx.x;
    if (e >= EE) return;
    if (!g_inside[e]) return;
    int i = idx_i[e];
    int p = g_rowptr[i] + atomicAdd(&g_fill[i], 1);
    g_csr[p] = e;
}

__global__ void init_kernel(const int* __restrict__ z, const float* __restrict__ emb) {
    int idx = blockIdx.x * blockDim.x + threadIdx.x;
    if (idx >= NN*64) return;
    int n = idx >> 6, fq = idx & 63;
    int f0 = fq * 2;
    int zi = z[n];
    float e0 = emb[zi*FF + f0];
    float e1 = emb[zi*FF + f0 + 1];
    g_sA[n*FF + f0]     = e0;
    g_sA[n*FF + f0 + 1] = e1;
    uint32_t h, l;
    split2(e0, e1, h, l);
    g_sH[idx] = h; g_sL[idx] = l;
    size_t vb = (size_t)n * F3 + f0;
    g_vA[vb] = 0.f;        g_vA[vb+1] = 0.f;
    g_vA[vb+FF] = 0.f;     g_vA[vb+FF+1] = 0.f;
    g_vA[vb+2*FF] = 0.f;   g_vA[vb+2*FF+1] = 0.f;
}

// transpose-pack ALL weights into split bf16 [N][K/2 uints] per matrix, per layer
__global__ void pack_w_kernel(const float* __restrict__ w1, const float* __restrict__ w2,
                              const float* __restrict__ U,  const float* __restrict__ V,
                              const float* __restrict__ u1, const float* __restrict__ u2) {
    int idx = blockIdx.x * blockDim.x + threadIdx.x;
    if (idx >= LL*PSu) return;
    int l = idx / PSu, r = idx % PSu;
    float v0, v1;
    if (r < OW2u) {                    // w1T [128][64u]
        int n = r >> 6, k0 = (r & 63) * 2;
        v0 = w1[(size_t)l*16384 + k0*128 + n];
        v1 = w1[(size_t)l*16384 + (k0+1)*128 + n];
    } else if (r < OUVu) {             // w2T [384][64u]
        int r2 = r - OW2u; int n = r2 >> 6, k0 = (r2 & 63) * 2;
        v0 = w2[(size_t)l*49152 + k0*384 + n];
        v1 = w2[(size_t)l*49152 + (k0+1)*384 + n];
    } else if (r < OU1u) {             // UVwT [256][64u] = U|V cols
        int r2 = r - OUVu; int n = r2 >> 6, k0 = (r2 & 63) * 2;
        if (n < 128) {
            v0 = U[(size_t)l*16384 + k0*128 + n];
            v1 = U[(size_t)l*16384 + (k0+1)*128 + n];
        } else {
            v0 = V[(size_t)l*16384 + k0*128 + (n-128)];
            v1 = V[(size_t)l*16384 + (k0+1)*128 + (n-128)];
        }
    } else if (r < OU2u) {             // u1T [128][128u]
        int r2 = r - OU1u; int n = r2 >> 7, k0 = (r2 & 127) * 2;
        v0 = u1[(size_t)l*32768 + k0*128 + n];
        v1 = u1[(size_t)l*32768 + (k0+1)*128 + n];
    } else {                           // u2T [384][64u]
        int r2 = r - OU2u; int n = r2 >> 6, k0 = (r2 & 63) * 2;
        v0 = u2[(size_t)l*49152 + k0*384 + n];
        v1 = u2[(size_t)l*49152 + (k0+1)*384 + n];
    }
    uint32_t h, l2;
    split2(v0, v1, h, l2);
    g_wH[idx] = h; g_wL[idx] = l2;
}

// ---------------- fused message kernel (also emits split vOut) --------------
// vz != 0: vIn is identically zero (layer 0) -> skip the vIn gathers.
__global__ __launch_bounds__(128) void msg_kernel(
    const float* __restrict__ sIn, const float* __restrict__ vIn,
    const float* __restrict__ phi,
    float* __restrict__ sOut, float* __restrict__ vOut,
    const int* __restrict__ idx_j,
    const float* __restrict__ rbw, const float* __restrict__ rbb, int vz)
{
    int f = threadIdx.x;
    float wvv[RR], wss[RR], wvs[RR];
    #pragma unroll
    for (int k = 0; k < RR; k++) {
        wvv[k] = rbw[k*F3 + f];
        wss[k] = rbw[k*F3 + FF + f];
        wvs[k] = rbw[k*F3 + 2*FF + f];
    }
    float bvv = rbb[f], bss = rbb[FF+f], bvs = rbb[2*FF+f];

    for (int i = blockIdx.x; i < NN; i += gridDim.x) {
        int p0 = g_rowptr[i], p1 = g_rowptr[i+1];
        float accs = 0.f, av0 = 0.f, av1 = 0.f, av2 = 0.f;
        for (int p = p0; p < p1; p++) {
            int e = g_csr[p];
            int j = idx_j[e];
            float cut = g_cut[e];
            float d0 = g_dir[e*3+0], d1 = g_dir[e*3+1], d2 = g_dir[e*3+2];
            float Wv = bvv*cut, Ws = bss*cut, Wq = bvs*cut;
            const float* rc = &g_rbfc[e*RR];
            #pragma unroll
            for (int k = 0; k < RR; k++) {
                float r = rc[k];
                Wv += r * wvv[k];
                Ws += r * wss[k];
                Wq += r * wvs[k];
            }
            const float* ph = &phi[(size_t)j * F3];
            float pvv = ph[f]        * Wv;
            float pss = ph[FF + f]   * Ws;
            float pvs = ph[2*FF + f] * Wq;
            accs += pss;
            if (vz) {
                av0 += pvs * d0;
                av1 += pvs * d1;
                av2 += pvs * d2;
            } else {
                const float* vj = &vIn[(size_t)j * F3];
                av0 += vj[f]        * pvv + pvs * d0;
                av1 += vj[FF + f]   * pvv + pvs * d1;
                av2 += vj[2*FF + f] * pvv + pvs * d2;
            }
        }
        sOut[(size_t)i*FF + f] = sIn[(size_t)i*FF + f] + accs;
        size_t vb = (size_t)i * F3;
        float n0, n1, n2;
        if (vz) { n0 = av0; n1 = av1; n2 = av2; }
        else {
            n0 = vIn[vb + f]        + av0;
            n1 = vIn[vb + FF + f]   + av1;
            n2 = vIn[vb + 2*FF + f] + av2;
        }
        vOut[vb + f]        = n0;
        vOut[vb + FF + f]   = n1;
        vOut[vb + 2*FF + f] = n2;
        // split pairs for the UV GEMM
        float q0 = __shfl_down_sync(0xFFFFFFFFu, n0, 1);
        float q1 = __shfl_down_sync(0xFFFFFFFFu, n1, 1);
        float q2 = __shfl_down_sync(0xFFFFFFFFu, n2, 1);
        if ((f & 1) == 0) {
            size_t rb = (size_t)i * 192 + (f >> 1);
            uint32_t h, l;
            split2(n0, q0, h, l); g_vH[rb]       = h; g_vL[rb]       = l;
            split2(n1, q1, h, l); g_vH[rb + 64]  = h; g_vL[rb + 64]  = l;
            split2(n2, q2, h, l); g_vH[rb + 128] = h; g_vL[rb + 128] = l;
        }
    }
}

// ---------------- x = concat(safe_norm(Vv), sfeat) -> split only ------------
__global__ void buildx_kernel(const float* __restrict__ s) {
    int idx = blockIdx.x * blockDim.x + threadIdx.x;
    if (idx >= NN*128) return;
    int n = idx >> 7, cq = idx & 127;
    int c0 = cq * 2;
    float x0, x1;
    if (c0 < FF) {
        size_t b = (size_t)n * 768 + 128 + c0;
        float v0 = g_UVv[b],   v1 = g_UVv[b + 256],   v2 = g_UVv[b + 512];
        float u0 = g_UVv[b+1], u1 = g_UVv[b + 257],   u2 = g_UVv[b + 513];
        float sq0 = v0*v0 + v1*v1 + v2*v2;
        float sq1 = u0*u0 + u1*u1 + u2*u2;
        x0 = (sq0 > 0.0f) ? sqrtf(sq0) : 0.0f;
        x1 = (sq1 > 0.0f) ? sqrtf(sq1) : 0.0f;
    } else {
        x0 = s[(size_t)n*FF + (c0 - FF)];
        x1 = s[(size_t)n*FF + (c0 - FF) + 1];
    }
    uint32_t h, l;
    split2(x0, x1, h, l);
    g_xH[idx] = h; g_xL[idx] = l;
}

// ---------------- update block (also emits split s) -------------------------
__global__ void update_kernel(float* __restrict__ s, float* __restrict__ v) {
    int idx = blockIdx.x * blockDim.x + threadIdx.x;
    if (idx >= NN*64) return;
    int n = idx >> 6, fq = idx & 63;
    int f0 = fq * 2, f1 = f0 + 1;
    size_t ub = (size_t)n * 768;
    float u00 = g_UVv[ub+f0], u01 = g_UVv[ub+256+f0], u02 = g_UVv[ub+512+f0];
    float u10 = g_UVv[ub+f1], u11 = g_UVv[ub+256+f1], u12 = g_UVv[ub+512+f1];
    float w00 = g_UVv[ub+128+f0], w01 = g_UVv[ub+384+f0], w02 = g_UVv[ub+640+f0];
    float w10 = g_UVv[ub+128+f1], w11 = g_UVv[ub+384+f1], w12 = g_UVv[ub+640+f1];
    float dot0 = u00*w00 + u01*w01 + u02*w02;
    float dot1 = u10*w10 + u11*w11 + u12*w12;
    const float* an = &g_a[(size_t)n * F3];
    float avv0 = an[f0], asv0 = an[FF+f0], ass0 = an[2*FF+f0];
    float avv1 = an[f1], asv1 = an[FF+f1], ass1 = an[2*FF+f1];
    size_t b = (size_t)n * F3 + f0;
    v[b]          += u00 * avv0;
    v[b + 1]      += u10 * avv1;
    v[b + FF]     += u01 * avv0;
    v[b + FF + 1] += u11 * avv1;
    v[b + 2*FF]     += u02 * avv0;
    v[b + 2*FF + 1] += u12 * avv1;
    float s0 = s[(size_t)n*FF + f0] + ass0 + asv0 * dot0;
    float s1 = s[(size_t)n*FF + f1] + ass1 + asv1 * dot1;
    s[(size_t)n*FF + f0] = s0;
    s[(size_t)n*FF + f1] = s1;
    uint32_t h, l;
    split2(s0, s1, h, l);
    g_sH[idx] = h; g_sL[idx] = l;
}

__global__ void output_kernel(const float* __restrict__ s, const float* __restrict__ v,
                              float* __restrict__ out) {
    int idx = blockIdx.x * blockDim.x + threadIdx.x;
    if (idx >= NN*FF) return;
    int n = idx / FF, f = idx % FF;
    out[idx] = s[idx];
    size_t ob = (size_t)NN*FF + (size_t)idx * 3;
    size_t vb = (size_t)n * F3 + f;
    out[ob + 0] = v[vb];
    out[ob + 1] = v[vb + FF];
    out[ob + 2] = v[vb + 2*FF];
}

// ---------------- host orchestration ----------------------------------------
static inline void launch_gemm(const uint32_t* AH, const uint32_t* AL,
                               const uint32_t* BH, const uint32_t* BL,
                               const float* bias, float* Cf,
                               uint32_t* CH, uint32_t* CL,
                               int M, int K, int N, int act) {
    dim3 grid(N / GBN, (M + GBM - 1) / GBM);
    gemm_bf16_kernel<<<grid, 256, GSMEM_BYTES>>>(AH, AL, BH, BL, bias, Cf, CH, CL, M, K, N, act);
}

extern "C" void kernel_launch(void* const* d_in, const int* in_sizes, int n_in,
                              void* d_out, int out_size) {
    const int*   z      = (const int*)  d_in[0];
    const float* pos    = (const float*)d_in[1];
    const int*   idx_i  = (const int*)  d_in[2];
    const int*   idx_j  = (const int*)  d_in[3];
    const float* emb    = (const float*)d_in[4];
    const float* msg_w1 = (const float*)d_in[5];
    const float* msg_b1 = (const float*)d_in[6];
    const float* msg_w2 = (const float*)d_in[7];
    const float* msg_b2 = (const float*)d_in[8];
    const float* rbf_w  = (const float*)d_in[9];
    const float* rbf_b  = (const float*)d_in[10];
    const float* upd_U  = (const float*)d_in[11];
    const float* upd_V  = (const float*)d_in[12];
    const float* upd_w1 = (const float*)d_in[13];
    const float* upd_b1 = (const float*)d_in[14];
    const float* upd_w2 = (const float*)d_in[15];
    const float* upd_b2 = (const float*)d_in[16];
    float* out = (float*)d_out;

    cudaFuncSetAttribute(gemm_bf16_kernel,
                         cudaFuncAttributeMaxDynamicSharedMemorySize, GSMEM_BYTES);
    cudaFuncSetAttribute(gemm_bf16_kernel,
                         cudaFuncAttributePreferredSharedMemoryCarveout, 100);

    float *sA, *sB, *vA, *vB, *phi, *UVv, *aa;
    cudaGetSymbolAddress((void**)&sA,  g_sA);
    cudaGetSymbolAddress((void**)&sB,  g_sB);
    cudaGetSymbolAddress((void**)&vA,  g_vA);
    cudaGetSymbolAddress((void**)&vB,  g_vB);
    cudaGetSymbolAddress((void**)&phi, g_phi);
    cudaGetSymbolAddress((void**)&UVv, g_UVv);
    cudaGetSymbolAddress((void**)&aa,  g_a);
    uint32_t *wH, *wL, *sH, *sL, *hidH, *hidL, *vH, *vL, *xH, *xL;
    cudaGetSymbolAddress((void**)&wH,   g_wH);
    cudaGetSymbolAddress((void**)&wL,   g_wL);
    cudaGetSymbolAddress((void**)&sH,   g_sH);
    cudaGetSymbolAddress((void**)&sL,   g_sL);
    cudaGetSymbolAddress((void**)&hidH, g_hidH);
    cudaGetSymbolAddress((void**)&hidL, g_hidL);
    cudaGetSymbolAddress((void**)&vH,   g_vH);
    cudaGetSymbolAddress((void**)&vL,   g_vL);
    cudaGetSymbolAddress((void**)&xH,   g_xH);
    cudaGetSymbolAddress((void**)&xL,   g_xL);

    // ---- setup (replayed each graph iteration; deterministic) ----
    pack_w_kernel<<<(LL*PSu + 255)/256, 256>>>(msg_w1, msg_w2, upd_U, upd_V, upd_w1, upd_w2);
    init_kernel<<<(NN*64 + 255)/256, 256>>>(z, emb);
    zero_counts_kernel<<<(NN + 255)/256, 256>>>();

    float* sCur = sA; float* sNxt = sB;
    float* vCur = vA; float* vNxt = vB;

    for (int l = 0; l < 3; l++) {
        const uint32_t* lwH = wH + (size_t)l * PSu;
        const uint32_t* lwL = wL + (size_t)l * PSu;
        // hid = silu(s @ w1 + b1)  [split out]
        launch_gemm(sH, sL, lwH + OW1u, lwL + OW1u, msg_b1 + (size_t)l*FF,
                    nullptr, hidH, hidL, NN, 128, 128, 1);
        if (l == 0) {
            edge_pre_kernel<<<(EE + 255)/256, 256>>>(pos, idx_i, idx_j);
            scan_kernel<<<1, 1024>>>();
            scatter_kernel<<<(EE + 255)/256, 256>>>(idx_i);
        }
        // phi = hid @ w2 + b2  [fp32 out]
        launch_gemm(hidH, hidL, lwH + OW2u, lwL + OW2u, msg_b2 + (size_t)l*F3,
                    phi, nullptr, nullptr, NN, 128, 384, 0);
        // message pass (writes fp32 + split v)
        msg_kernel<<<2000, 128>>>(sCur, vCur, phi, sNxt, vNxt, idx_j,
                                  rbf_w + (size_t)l*RR*F3, rbf_b + (size_t)l*F3,
                                  (l == 0) ? 1 : 0);
        // [Uv | Vv] = vNxt[3N,F] @ UVw[F,2F]  [fp32 out]
        launch_gemm(vH, vL, lwH + OUVu, lwL + OUVu, nullptr,
                    UVv, nullptr, nullptr, 3*NN, 128, 256, 0);
        // x = concat(||Vv||, s) -> split only
        buildx_kernel<<<(NN*128 + 255)/256, 256>>>(sNxt);
        // hid = silu(x @ uw1 + ub1)  [split out]
        launch_gemm(xH, xL, lwH + OU1u, lwL + OU1u, upd_b1 + (size_t)l*FF,
                    nullptr, hidH, hidL, NN, 256, 128, 1);
        // a = hid @ uw2 + ub2  [fp32 out]
        launch_gemm(hidH, hidL, lwH + OU2u, lwL + OU2u, upd_b2 + (size_t)l*F3,
                    aa, nullptr, nullptr, NN, 128, 384, 0);
        // in-place update (also refreshes split s)
        update_kernel<<<(NN*64 + 255)/256, 256>>>(sNxt, vNxt);

        float* t;
        t = sCur; sCur = sNxt; sNxt = t;
        t = vCur; vCur = vNxt; vNxt = t;
    }

    output_kernel<<<(NN*FF + 255)/256, 256>>>(sCur, vCur, out);
}

// round 15
// speedup vs baseline: 1.1136x; 1.1136x over previous
#include <cuda_runtime.h>
#include <cstdint>
#include <math.h>

#ifndef M_PI
#define M_PI 3.14159265358979323846
#endif

#define NN 10000
#define EE 160000
#define FF 128
#define RR 20
#define F3 (3*FF)
#define CUT_D 3.0f
#define LL 3

// packed split-weight layout, uints per layer
#define PSu  90112
#define OW1u 0          /* w1T  [128][64u]  */
#define OW2u 8192       /* w2T  [384][64u]  */
#define OUVu 32768      /* UVwT [256][64u]  */
#define OU1u 49152      /* u1T  [128][128u] */
#define OU2u 65536      /* u2T  [384][64u]  */

// ---------------- scratch (device globals; no allocation allowed) ----------
__device__ float g_rbfc[EE*RR];
__device__ float g_cut[EE];
__device__ float g_dir[EE*3];
__device__ int   g_inside[EE];
__device__ int   g_deg[NN];
__device__ int   g_rowptr[NN+1];
__device__ int   g_fill[NN];
__device__ int   g_csr[EE];
__device__ float g_sA[NN*FF], g_sB[NN*FF];
__device__ float g_vA[NN*3*FF], g_vB[NN*3*FF];   // stored [N,3,F]
__device__ float g_phi[NN*F3];
__device__ float g_UVv[NN*3*2*FF];               // [3N][256]: Uv | Vv
__device__ float g_a[NN*F3];
// split bf16 hi/lo packed operands (uint = bf16x2, even elem in low half)
__device__ __align__(16) uint32_t g_wH[LL*PSu],  g_wL[LL*PSu];
__device__ __align__(16) uint32_t g_sH[NN*64],   g_sL[NN*64];
__device__ __align__(16) uint32_t g_hidH[NN*64], g_hidL[NN*64];
__device__ __align__(16) uint32_t g_vH[NN*192],  g_vL[NN*192];   // [3N][64u]
__device__ __align__(16) uint32_t g_xH[NN*128],  g_xL[NN*128];   // [N][128u]

// ---------------- bf16 split helpers ----------------------------------------
__device__ __forceinline__ uint32_t bf16bits_hi(float x) {
    uint32_t u = __float_as_uint(x);
    return (u + 0x7FFFu + ((u >> 16) & 1u)) & 0xFFFF0000u;   // float bits of rn(bf16)
}
__device__ __forceinline__ void split2(float x, float y, uint32_t& hi2, uint32_t& lo2) {
    uint32_t hx = bf16bits_hi(x);
    uint32_t hy = bf16bits_hi(y);
    float lx = x - __uint_as_float(hx);
    float ly = y - __uint_as_float(hy);
    hi2 = (hx >> 16) | hy;
    lo2 = (bf16bits_hi(lx) >> 16) | bf16bits_hi(ly);
}
__device__ __forceinline__ float silu_fast(float x) {
    return __fdividef(x, 1.0f + __expf(-x));
}

__device__ __forceinline__ uint32_t smem_u32(const void* p) {
    uint32_t a;
    asm("{ .reg .u64 t; cvta.to.shared.u64 t, %1; cvt.u32.u64 %0, t; }"
        : "=r"(a) : "l"(p));
    return a;
}
__device__ __forceinline__ void cp_async16(uint32_t dst, const void* src, int srcBytes) {
    asm volatile("cp.async.cg.shared.global [%0], [%1], 16, %2;"
                 :: "r"(dst), "l"(src), "r"(srcBytes) : "memory");
}
__device__ __forceinline__ void cp_commit() {
    asm volatile("cp.async.commit_group;" ::: "memory");
}
// m16n8k16 bf16 MMA: a = {a0,a1,a2,a3}, b = {b0,b1}
__device__ __forceinline__ void mma_bf16_k16(float* c, const uint32_t* a, const uint32_t* b) {
    asm volatile(
        "mma.sync.aligned.m16n8k16.row.col.f32.bf16.bf16.f32 "
        "{%0,%1,%2,%3}, {%4,%5,%6,%7}, {%8,%9}, {%0,%1,%2,%3};"
        : "+f"(c[0]), "+f"(c[1]), "+f"(c[2]), "+f"(c[3])
        : "r"(a[0]), "r"(a[1]), "r"(a[2]), "r"(a[3]), "r"(b[0]), "r"(b[1]));
}

// ================= bf16x3 mma.sync GEMM (k16, templated tile height) ========
// Rows per CTA = MT*32 (MT=2 -> 64, MT=4 -> 128). N mult of 64, K mult of 32.
// C[M,N] = act(A[M,K] @ BT[N,K]^T + bias). A,B packed split bf16.
#define GBN 64
#define USTR 20
#define BTSg (64*USTR)           /* 1280u per B matrix */

template<int MT>
__global__ __launch_bounds__(256) void gemm_bf16_kernel(
    const uint32_t* __restrict__ AH, const uint32_t* __restrict__ AL,
    const uint32_t* __restrict__ BH, const uint32_t* __restrict__ BL,
    const float* __restrict__ bias, float* __restrict__ Cf,
    uint32_t* __restrict__ CH, uint32_t* __restrict__ CL,
    int M, int K, int N, int act)
{
    constexpr int ROWS = MT * 32;
    constexpr int ATS  = ROWS * USTR;           // uints per A matrix (hi or lo)
    constexpr int STGU = 2*ATS + 2*BTSg;        // one stage
    extern __shared__ __align__(16) uint32_t sm[];
    uint32_t sb = smem_u32(sm);
    int tid  = threadIdx.x;
    int lane = tid & 31;
    int warp = tid >> 5;
    int wm = warp & 1;                  // 2 warps along M (ROWS/2 each)
    int wn = warp >> 1;                 // 4 warps along N (16 cols each)
    int g  = lane >> 2;
    int t  = lane & 3;
    int rowBase = blockIdx.y * ROWS;
    int colBase = blockIdx.x * GBN;
    int K2 = K >> 1;

    int lrow = tid >> 2;                // 0..63
    int lq   = tid & 3;                 // float4 slot (4 uints)

    float acc[MT][2][4];
    #pragma unroll
    for (int mt = 0; mt < MT; mt++)
        #pragma unroll
        for (int nt = 0; nt < 2; nt++)
            #pragma unroll
            for (int q = 0; q < 4; q++) acc[mt][nt][q] = 0.0f;

    int chunks = K >> 5;

    auto loadChunk = [&](int c) {
        if (c < chunks) {
            int s = c & 1;
            int k0u = c << 4;
            uint32_t base = sb + (uint32_t)(s * STGU) * 4u;
            #pragma unroll
            for (int it = 0; it < MT/2; it++) {
                int r = lrow + it * 64;
                int gr = rowBase + r;
                int ok = (gr < M);
                size_t off = (size_t)(ok ? gr : 0) * K2 + k0u + lq * 4;
                uint32_t dr = base + (uint32_t)(r * USTR + lq * 4) * 4u;
                cp_async16(dr, &AH[off], ok ? 16 : 0);
                cp_async16(dr + (uint32_t)ATS * 4u, &AL[off], ok ? 16 : 0);
            }
            size_t boff = (size_t)(colBase + lrow) * K2 + k0u + lq * 4;
            uint32_t db = base + (uint32_t)(2*ATS + lrow * USTR + lq * 4) * 4u;
            cp_async16(db, &BH[boff], 16);
            cp_async16(db + (uint32_t)BTSg * 4u, &BL[boff], 16);
        }
        cp_commit();
    };

    loadChunk(0);
    loadChunk(1);

    for (int c = 0; c < chunks; c++) {
        asm volatile("cp.async.wait_group 1;" ::: "memory");
        __syncthreads();

        const uint32_t* st = sm + (c & 1) * STGU;
        #pragma unroll
        for (int ks = 0; ks < 2; ks++) {                 // two k16 steps per chunk
            uint32_t bHf[2][2], bLf[2][2];
            #pragma unroll
            for (int nt = 0; nt < 2; nt++) {
                int uo = 2*ATS + (wn*16 + nt*8 + g) * USTR + ks*8 + t;
                bHf[nt][0] = st[uo];
                bHf[nt][1] = st[uo + 4];
                bLf[nt][0] = st[BTSg + uo];
                bLf[nt][1] = st[BTSg + uo + 4];
            }
            #pragma unroll
            for (int mt = 0; mt < MT; mt++) {
                uint32_t aHf[4], aLf[4];
                int uo = (wm*(ROWS/2) + mt*16 + g) * USTR + ks*8 + t;
                aHf[0] = st[uo];
                aHf[1] = st[uo + 8*USTR];
                aHf[2] = st[uo + 4];
                aHf[3] = st[uo + 4 + 8*USTR];
                aLf[0] = st[ATS + uo];
                aLf[1] = st[ATS + uo + 8*USTR];
                aLf[2] = st[ATS + uo + 4];
                aLf[3] = st[ATS + uo + 4 + 8*USTR];
                #pragma unroll
                for (int nt = 0; nt < 2; nt++) {
                    mma_bf16_k16(acc[mt][nt], aHf, bHf[nt]);
                    mma_bf16_k16(acc[mt][nt], aHf, bLf[nt]);
                    mma_bf16_k16(acc[mt][nt], aLf, bHf[nt]);
                }
            }
        }
        __syncthreads();
        loadChunk(c + 2);
    }

    // ---- epilogue ----
    int N2 = N >> 1;
    #pragma unroll
    for (int mt = 0; mt < MT; mt++) {
        int r0 = rowBase + wm*(ROWS/2) + mt*16 + g;
        int r1 = r0 + 8;
        #pragma unroll
        for (int nt = 0; nt < 2; nt++) {
            int cc = colBase + wn*16 + nt*8 + t*2;
            float b0 = 0.f, b1 = 0.f;
            if (bias) { b0 = bias[cc]; b1 = bias[cc+1]; }
            float o0 = acc[mt][nt][0] + b0;
            float o1 = acc[mt][nt][1] + b1;
            float o2 = acc[mt][nt][2] + b0;
            float o3 = acc[mt][nt][3] + b1;
            if (act == 1) {
                o0 = silu_fast(o0);
                o1 = silu_fast(o1);
                o2 = silu_fast(o2);
                o3 = silu_fast(o3);
            }
            if (CH) {
                uint32_t h, l;
                if (r0 < M) {
                    split2(o0, o1, h, l);
                    CH[(size_t)r0*N2 + (cc>>1)] = h;
                    CL[(size_t)r0*N2 + (cc>>1)] = l;
                }
                if (r1 < M) {
                    split2(o2, o3, h, l);
                    CH[(size_t)r1*N2 + (cc>>1)] = h;
                    CL[(size_t)r1*N2 + (cc>>1)] = l;
                }
            } else {
                if (r0 < M) *(float2*)&Cf[(size_t)r0*N + cc] = make_float2(o0, o1);
                if (r1 < M) *(float2*)&Cf[(size_t)r1*N + cc] = make_float2(o2, o3);
            }
        }
    }
}

#define SM_BYTES_MT2 ((2*(2*(64*USTR) + 2*BTSg))*4)    /* 40960  */
#define SM_BYTES_MT4 ((2*(2*(128*USTR) + 2*BTSg))*4)   /* 61440  */

// ================= graph-structure + elementwise kernels =====================
__global__ void zero_counts_kernel() {
    int i = blockIdx.x * blockDim.x + threadIdx.x;
    if (i < NN) { g_deg[i] = 0; g_fill[i] = 0; }
}

__global__ void edge_pre_kernel(const float* __restrict__ pos,
                                const int* __restrict__ idx_i,
                                const int* __restrict__ idx_j) {
    int e = blockIdx.x * blockDim.x + threadIdx.x;
    if (e >= EE) return;
    int i = idx_i[e], j = idx_j[e];
    float rx = pos[j*3+0] - pos[i*3+0];
    float ry = pos[j*3+1] - pos[i*3+1];
    float rz = pos[j*3+2] - pos[i*3+2];
    float sq = rx*rx + ry*ry + rz*rz;
    float d  = sqrtf(sq);
    float inv = 1.0f / d;
    g_dir[e*3+0] = rx*inv;
    g_dir[e*3+1] = ry*inv;
    g_dir[e*3+2] = rz*inv;
    int ins = (d < CUT_D) ? 1 : 0;
    float base = (float)M_PI * d / CUT_D;
    float s1, c1;
    sincosf(base, &s1, &c1);
    float cut = ins ? 0.5f * (c1 + 1.0f) : 0.0f;
    g_cut[e] = cut;
    g_inside[e] = ins;
    float ic = inv * cut;
    float twoc = 2.0f * c1;
    float sk = s1, skm1 = 0.0f;
    #pragma unroll
    for (int k = 0; k < RR; k++) {
        g_rbfc[e*RR+k] = sk * ic;
        float nxt = twoc * sk - skm1;
        skm1 = sk; sk = nxt;
    }
    if (ins) atomicAdd(&g_deg[i], 1);
}

// warp-shuffle single-block scan (1024 threads, 32 warps)
__global__ void scan_kernel() {
    __shared__ int wsum[32];
    __shared__ int carry;
    int tid = threadIdx.x, lane = tid & 31, wid = tid >> 5;
    if (tid == 0) { carry = 0; g_rowptr[0] = 0; }
    __syncthreads();
    for (int base = 0; base < NN; base += 1024) {
        int i = base + tid;
        int x = (i < NN) ? g_deg[i] : 0;
        #pragma unroll
        for (int off = 1; off < 32; off <<= 1) {
            int y = __shfl_up_sync(0xFFFFFFFFu, x, off);
            if (lane >= off) x += y;
        }
        if (lane == 31) wsum[wid] = x;
        __syncthreads();
        if (wid == 0) {
            int s = wsum[lane];
            #pragma unroll
            for (int off = 1; off < 32; off <<= 1) {
                int y = __shfl_up_sync(0xFFFFFFFFu, s, off);
                if (lane >= off) s += y;
            }
            wsum[lane] = s;
        }
        __syncthreads();
        int pre = (wid > 0) ? wsum[wid - 1] : 0;
        int inc = x + pre + carry;
        if (i < NN) g_rowptr[i + 1] = inc;
        __syncthreads();
        if (tid == 1023) carry = inc;
        __syncthreads();
    }
}

__global__ void scatter_kernel(const int* __restrict__ idx_i) {
    int e = blockIdx.x * blockDim.x + threadIdx.x;
    if (e >= EE) return;
    if (!g_inside[e]) return;
    int i = idx_i[e];
    int p = g_rowptr[i] + atomicAdd(&g_fill[i], 1);
    g_csr[p] = e;
}

__global__ void init_kernel(const int* __restrict__ z, const float* __restrict__ emb) {
    int idx = blockIdx.x * blockDim.x + threadIdx.x;
    if (idx >= NN*64) return;
    int n = idx >> 6, fq = idx & 63;
    int f0 = fq * 2;
    int zi = z[n];
    float e0 = emb[zi*FF + f0];
    float e1 = emb[zi*FF + f0 + 1];
    g_sA[n*FF + f0]     = e0;
    g_sA[n*FF + f0 + 1] = e1;
    uint32_t h, l;
    split2(e0, e1, h, l);
    g_sH[idx] = h; g_sL[idx] = l;
    size_t vb = (size_t)n * F3 + f0;
    g_vA[vb] = 0.f;        g_vA[vb+1] = 0.f;
    g_vA[vb+FF] = 0.f;     g_vA[vb+FF+1] = 0.f;
    g_vA[vb+2*FF] = 0.f;   g_vA[vb+2*FF+1] = 0.f;
}

// transpose-pack ALL weights into split bf16 [N][K/2 uints] per matrix, per layer
__global__ void pack_w_kernel(const float* __restrict__ w1, const float* __restrict__ w2,
                              const float* __restrict__ U,  const float* __restrict__ V,
                              const float* __restrict__ u1, const float* __restrict__ u2) {
    int idx = blockIdx.x * blockDim.x + threadIdx.x;
    if (idx >= LL*PSu) return;
    int l = idx / PSu, r = idx % PSu;
    float v0, v1;
    if (r < OW2u) {                    // w1T [128][64u]
        int n = r >> 6, k0 = (r & 63) * 2;
        v0 = w1[(size_t)l*16384 + k0*128 + n];
        v1 = w1[(size_t)l*16384 + (k0+1)*128 + n];
    } else if (r < OUVu) {             // w2T [384][64u]
        int r2 = r - OW2u; int n = r2 >> 6, k0 = (r2 & 63) * 2;
        v0 = w2[(size_t)l*49152 + k0*384 + n];
        v1 = w2[(size_t)l*49152 + (k0+1)*384 + n];
    } else if (r < OU1u) {             // UVwT [256][64u] = U|V cols
        int r2 = r - OUVu; int n = r2 >> 6, k0 = (r2 & 63) * 2;
        if (n < 128) {
            v0 = U[(size_t)l*16384 + k0*128 + n];
            v1 = U[(size_t)l*16384 + (k0+1)*128 + n];
        } else {
            v0 = V[(size_t)l*16384 + k0*128 + (n-128)];
            v1 = V[(size_t)l*16384 + (k0+1)*128 + (n-128)];
        }
    } else if (r < OU2u) {             // u1T [128][128u]
        int r2 = r - OU1u; int n = r2 >> 7, k0 = (r2 & 127) * 2;
        v0 = u1[(size_t)l*32768 + k0*128 + n];
        v1 = u1[(size_t)l*32768 + (k0+1)*128 + n];
    } else {                           // u2T [384][64u]
        int r2 = r - OU2u; int n = r2 >> 6, k0 = (r2 & 63) * 2;
        v0 = u2[(size_t)l*49152 + k0*384 + n];
        v1 = u2[(size_t)l*49152 + (k0+1)*384 + n];
    }
    uint32_t h, l2;
    split2(v0, v1, h, l2);
    g_wH[idx] = h; g_wL[idx] = l2;
}

// ---------------- fused message kernel (also emits split vOut) --------------
// vz != 0: vIn is identically zero (layer 0) -> skip the vIn gathers.
__global__ __launch_bounds__(128) void msg_kernel(
    const float* __restrict__ sIn, const float* __restrict__ vIn,
    const float* __restrict__ phi,
    float* __restrict__ sOut, float* __restrict__ vOut,
    const int* __restrict__ idx_j,
    const float* __restrict__ rbw, const float* __restrict__ rbb, int vz)
{
    int f = threadIdx.x;
    float wvv[RR], wss[RR], wvs[RR];
    #pragma unroll
    for (int k = 0; k < RR; k++) {
        wvv[k] = rbw[k*F3 + f];
        wss[k] = rbw[k*F3 + FF + f];
        wvs[k] = rbw[k*F3 + 2*FF + f];
    }
    float bvv = rbb[f], bss = rbb[FF+f], bvs = rbb[2*FF+f];

    for (int i = blockIdx.x; i < NN; i += gridDim.x) {
        int p0 = g_rowptr[i], p1 = g_rowptr[i+1];
        float accs = 0.f, av0 = 0.f, av1 = 0.f, av2 = 0.f;
        for (int p = p0; p < p1; p++) {
            int e = g_csr[p];
            int j = idx_j[e];
            float cut = g_cut[e];
            float d0 = g_dir[e*3+0], d1 = g_dir[e*3+1], d2 = g_dir[e*3+2];
            float Wv = bvv*cut, Ws = bss*cut, Wq = bvs*cut;
            const float* rc = &g_rbfc[e*RR];
            #pragma unroll
            for (int k = 0; k < RR; k++) {
                float r = rc[k];
                Wv += r * wvv[k];
                Ws += r * wss[k];
                Wq += r * wvs[k];
            }
            const float* ph = &phi[(size_t)j * F3];
            float pvv = ph[f]        * Wv;
            float pss = ph[FF + f]   * Ws;
            float pvs = ph[2*FF + f] * Wq;
            accs += pss;
            if (vz) {
                av0 += pvs * d0;
                av1 += pvs * d1;
                av2 += pvs * d2;
            } else {
                const float* vj = &vIn[(size_t)j * F3];
                av0 += vj[f]        * pvv + pvs * d0;
                av1 += vj[FF + f]   * pvv + pvs * d1;
                av2 += vj[2*FF + f] * pvv + pvs * d2;
            }
        }
        sOut[(size_t)i*FF + f] = sIn[(size_t)i*FF + f] + accs;
        size_t vb = (size_t)i * F3;
        float n0, n1, n2;
        if (vz) { n0 = av0; n1 = av1; n2 = av2; }
        else {
            n0 = vIn[vb + f]        + av0;
            n1 = vIn[vb + FF + f]   + av1;
            n2 = vIn[vb + 2*FF + f] + av2;
        }
        vOut[vb + f]        = n0;
        vOut[vb + FF + f]   = n1;
        vOut[vb + 2*FF + f] = n2;
        // split pairs for the UV GEMM
        float q0 = __shfl_down_sync(0xFFFFFFFFu, n0, 1);
        float q1 = __shfl_down_sync(0xFFFFFFFFu, n1, 1);
        float q2 = __shfl_down_sync(0xFFFFFFFFu, n2, 1);
        if ((f & 1) == 0) {
            size_t rb = (size_t)i * 192 + (f >> 1);
            uint32_t h, l;
            split2(n0, q0, h, l); g_vH[rb]       = h; g_vL[rb]       = l;
            split2(n1, q1, h, l); g_vH[rb + 64]  = h; g_vL[rb + 64]  = l;
            split2(n2, q2, h, l); g_vH[rb + 128] = h; g_vL[rb + 128] = l;
        }
    }
}

// ---------------- x = concat(safe_norm(Vv), sfeat) -> split only ------------
__global__ void buildx_kernel(const float* __restrict__ s) {
    int idx = blockIdx.x * blockDim.x + threadIdx.x;
    if (idx >= NN*128) return;
    int n = idx >> 7, cq = idx & 127;
    int c0 = cq * 2;
    float x0, x1;
    if (c0 < FF) {
        size_t b = (size_t)n * 768 + 128 + c0;
        float v0 = g_UVv[b],   v1 = g_UVv[b + 256],   v2 = g_UVv[b + 512];
        float u0 = g_UVv[b+1], u1 = g_UVv[b + 257],   u2 = g_UVv[b + 513];
        float sq0 = v0*v0 + v1*v1 + v2*v2;
        float sq1 = u0*u0 + u1*u1 + u2*u2;
        x0 = (sq0 > 0.0f) ? sqrtf(sq0) : 0.0f;
        x1 = (sq1 > 0.0f) ? sqrtf(sq1) : 0.0f;
    } else {
        x0 = s[(size_t)n*FF + (c0 - FF)];
        x1 = s[(size_t)n*FF + (c0 - FF) + 1];
    }
    uint32_t h, l;
    split2(x0, x1, h, l);
    g_xH[idx] = h; g_xL[idx] = l;
}

// ---------------- update block (also emits split s) -------------------------
__global__ void update_kernel(float* __restrict__ s, float* __restrict__ v) {
    int idx = blockIdx.x * blockDim.x + threadIdx.x;
    if (idx >= NN*64) return;
    int n = idx >> 6, fq = idx & 63;
    int f0 = fq * 2, f1 = f0 + 1;
    size_t ub = (size_t)n * 768;
    float u00 = g_UVv[ub+f0], u01 = g_UVv[ub+256+f0], u02 = g_UVv[ub+512+f0];
    float u10 = g_UVv[ub+f1], u11 = g_UVv[ub+256+f1], u12 = g_UVv[ub+512+f1];
    float w00 = g_UVv[ub+128+f0], w01 = g_UVv[ub+384+f0], w02 = g_UVv[ub+640+f0];
    float w10 = g_UVv[ub+128+f1], w11 = g_UVv[ub+384+f1], w12 = g_UVv[ub+640+f1];
    float dot0 = u00*w00 + u01*w01 + u02*w02;
    float dot1 = u10*w10 + u11*w11 + u12*w12;
    const float* an = &g_a[(size_t)n * F3];
    float avv0 = an[f0], asv0 = an[FF+f0], ass0 = an[2*FF+f0];
    float avv1 = an[f1], asv1 = an[FF+f1], ass1 = an[2*FF+f1];
    size_t b = (size_t)n * F3 + f0;
    v[b]          += u00 * avv0;
    v[b + 1]      += u10 * avv1;
    v[b + FF]     += u01 * avv0;
    v[b + FF + 1] += u11 * avv1;
    v[b + 2*FF]     += u02 * avv0;
    v[b + 2*FF + 1] += u12 * avv1;
    float s0 = s[(size_t)n*FF + f0] + ass0 + asv0 * dot0;
    float s1 = s[(size_t)n*FF + f1] + ass1 + asv1 * dot1;
    s[(size_t)n*FF + f0] = s0;
    s[(size_t)n*FF + f1] = s1;
    uint32_t h, l;
    split2(s0, s1, h, l);
    g_sH[idx] = h; g_sL[idx] = l;
}

__global__ void output_kernel(const float* __restrict__ s, const float* __restrict__ v,
                              float* __restrict__ out) {
    int idx = blockIdx.x * blockDim.x + threadIdx.x;
    if (idx >= NN*FF) return;
    int n = idx / FF, f = idx % FF;
    out[idx] = s[idx];
    size_t ob = (size_t)NN*FF + (size_t)idx * 3;
    size_t vb = (size_t)n * F3 + f;
    out[ob + 0] = v[vb];
    out[ob + 1] = v[vb + FF];
    out[ob + 2] = v[vb + 2*FF];
}

// ---------------- host orchestration ----------------------------------------
static inline void launch_gemm64(const uint32_t* AH, const uint32_t* AL,
                                 const uint32_t* BH, const uint32_t* BL,
                                 const float* bias, float* Cf,
                                 uint32_t* CH, uint32_t* CL,
                                 int M, int K, int N, int act) {
    dim3 grid(N / GBN, (M + 63) / 64);
    gemm_bf16_kernel<2><<<grid, 256, SM_BYTES_MT2>>>(AH, AL, BH, BL, bias, Cf, CH, CL, M, K, N, act);
}
static inline void launch_gemm128(const uint32_t* AH, const uint32_t* AL,
                                  const uint32_t* BH, const uint32_t* BL,
                                  const float* bias, float* Cf,
                                  uint32_t* CH, uint32_t* CL,
                                  int M, int K, int N, int act) {
    dim3 grid(N / GBN, (M + 127) / 128);
    gemm_bf16_kernel<4><<<grid, 256, SM_BYTES_MT4>>>(AH, AL, BH, BL, bias, Cf, CH, CL, M, K, N, act);
}

extern "C" void kernel_launch(void* const* d_in, const int* in_sizes, int n_in,
                              void* d_out, int out_size) {
    const int*   z      = (const int*)  d_in[0];
    const float* pos    = (const float*)d_in[1];
    const int*   idx_i  = (const int*)  d_in[2];
    const int*   idx_j  = (const int*)  d_in[3];
    const float* emb    = (const float*)d_in[4];
    const float* msg_w1 = (const float*)d_in[5];
    const float* msg_b1 = (const float*)d_in[6];
    const float* msg_w2 = (const float*)d_in[7];
    const float* msg_b2 = (const float*)d_in[8];
    const float* rbf_w  = (const float*)d_in[9];
    const float* rbf_b  = (const float*)d_in[10];
    const float* upd_U  = (const float*)d_in[11];
    const float* upd_V  = (const float*)d_in[12];
    const float* upd_w1 = (const float*)d_in[13];
    const float* upd_b1 = (const float*)d_in[14];
    const float* upd_w2 = (const float*)d_in[15];
    const float* upd_b2 = (const float*)d_in[16];
    float* out = (float*)d_out;

    cudaFuncSetAttribute(gemm_bf16_kernel<2>,
                         cudaFuncAttributeMaxDynamicSharedMemorySize, SM_BYTES_MT2);
    cudaFuncSetAttribute(gemm_bf16_kernel<4>,
                         cudaFuncAttributeMaxDynamicSharedMemorySize, SM_BYTES_MT4);

    float *sA, *sB, *vA, *vB, *phi, *UVv, *aa;
    cudaGetSymbolAddress((void**)&sA,  g_sA);
    cudaGetSymbolAddress((void**)&sB,  g_sB);
    cudaGetSymbolAddress((void**)&vA,  g_vA);
    cudaGetSymbolAddress((void**)&vB,  g_vB);
    cudaGetSymbolAddress((void**)&phi, g_phi);
    cudaGetSymbolAddress((void**)&UVv, g_UVv);
    cudaGetSymbolAddress((void**)&aa,  g_a);
    uint32_t *wH, *wL, *sH, *sL, *hidH, *hidL, *vH, *vL, *xH, *xL;
    cudaGetSymbolAddress((void**)&wH,   g_wH);
    cudaGetSymbolAddress((void**)&wL,   g_wL);
    cudaGetSymbolAddress((void**)&sH,   g_sH);
    cudaGetSymbolAddress((void**)&sL,   g_sL);
    cudaGetSymbolAddress((void**)&hidH, g_hidH);
    cudaGetSymbolAddress((void**)&hidL, g_hidL);
    cudaGetSymbolAddress((void**)&vH,   g_vH);
    cudaGetSymbolAddress((void**)&vL,   g_vL);
    cudaGetSymbolAddress((void**)&xH,   g_xH);
    cudaGetSymbolAddress((void**)&xL,   g_xL);

    // ---- setup (replayed each graph iteration; deterministic) ----
    pack_w_kernel<<<(LL*PSu + 255)/256, 256>>>(msg_w1, msg_w2, upd_U, upd_V, upd_w1, upd_w2);
    init_kernel<<<(NN*64 + 255)/256, 256>>>(z, emb);
    zero_counts_kernel<<<(NN + 255)/256, 256>>>();

    float* sCur = sA; float* sNxt = sB;
    float* vCur = vA; float* vNxt = vB;

    for (int l = 0; l < 3; l++) {
        const uint32_t* lwH = wH + (size_t)l * PSu;
        const uint32_t* lwL = wL + (size_t)l * PSu;
        // hid = silu(s @ w1 + b1)  [split out]  M=10000, N=128 -> 64-row tiles
        launch_gemm64(sH, sL, lwH + OW1u, lwL + OW1u, msg_b1 + (size_t)l*FF,
                      nullptr, hidH, hidL, NN, 128, 128, 1);
        if (l == 0) {
            edge_pre_kernel<<<(EE + 255)/256, 256>>>(pos, idx_i, idx_j);
            scan_kernel<<<1, 1024>>>();
            scatter_kernel<<<(EE + 255)/256, 256>>>(idx_i);
        }
        // phi = hid @ w2 + b2  [fp32 out]
        launch_gemm128(hidH, hidL, lwH + OW2u, lwL + OW2u, msg_b2 + (size_t)l*F3,
                       phi, nullptr, nullptr, NN, 128, 384, 0);
        // message pass (writes fp32 + split v); one node per block
        msg_kernel<<<NN, 128>>>(sCur, vCur, phi, sNxt, vNxt, idx_j,
                                rbf_w + (size_t)l*RR*F3, rbf_b + (size_t)l*F3,
                                (l == 0) ? 1 : 0);
        // [Uv | Vv] = vNxt[3N,F] @ UVw[F,2F]  [fp32 out]
        launch_gemm128(vH, vL, lwH + OUVu, lwL + OUVu, nullptr,
                       UVv, nullptr, nullptr, 3*NN, 128, 256, 0);
        // x = concat(||Vv||, s) -> split only
        buildx_kernel<<<(NN*128 + 255)/256, 256>>>(sNxt);
        // hid = silu(x @ uw1 + ub1)  [split out]  M=10000, N=128 -> 64-row tiles
        launch_gemm64(xH, xL, lwH + OU1u, lwL + OU1u, upd_b1 + (size_t)l*FF,
                      nullptr, hidH, hidL, NN, 256, 128, 1);
        // a = hid @ uw2 + ub2  [fp32 out]
        launch_gemm128(hidH, hidL, lwH + OU2u, lwL + OU2u, upd_b2 + (size_t)l*F3,
                       aa, nullptr, nullptr, NN, 128, 384, 0);
        // in-place update (also refreshes split s)
        update_kernel<<<(NN*64 + 255)/256, 256>>>(sNxt, vNxt);

        float* t;
        t = sCur; sCur = sNxt; sNxt = t;
        t = vCur; vCur = vNxt; vNxt = t;
    }

    output_kernel<<<(NN*FF + 255)/256, 256>>>(sCur, vCur, out);
}

// round 16
// speedup vs baseline: 1.2212x; 1.0966x over previous
#include <cuda_runtime.h>
#include <cstdint>
#include <math.h>

#ifndef M_PI
#define M_PI 3.14159265358979323846
#endif

#define NN 10000
#define EE 160000
#define FF 128
#define RR 20
#define F3 (3*FF)
#define CUT_D 3.0f
#define LL 3

// packed split-weight layout, uints per layer
#define PSu  90112
#define OW1u 0          /* w1T  [128][64u]  */
#define OW2u 8192       /* w2T  [384][64u]  */
#define OUVu 32768      /* UVwT [256][64u]  */
#define OU1u 49152      /* u1T  [128][128u] */
#define OU2u 65536      /* u2T  [384][64u]  */

// ---------------- scratch (device globals; no allocation allowed) ----------
__device__ float g_rbfc[EE*RR];
__device__ float g_cut[EE];
__device__ float g_dir[EE*3];
__device__ int   g_inside[EE];
__device__ int   g_deg[NN];
__device__ int   g_rowptr[NN+1];
__device__ int   g_fill[NN];
__device__ int   g_csr[EE];
__device__ float g_sA[NN*FF], g_sB[NN*FF];
__device__ float g_vA[NN*3*FF], g_vB[NN*3*FF];   // stored [N,3,F]
__device__ float g_phi[NN*F3];
__device__ float g_UVv[NN*3*2*FF];               // [3N][256]: Uv | Vv
__device__ float g_a[NN*F3];
// split bf16 hi/lo packed operands (uint = bf16x2, even elem in low half)
__device__ __align__(16) uint32_t g_wH[LL*PSu],  g_wL[LL*PSu];
__device__ __align__(16) uint32_t g_sH[NN*64],   g_sL[NN*64];
__device__ __align__(16) uint32_t g_hidH[NN*64], g_hidL[NN*64];
__device__ __align__(16) uint32_t g_vH[NN*192],  g_vL[NN*192];   // [3N][64u]
__device__ __align__(16) uint32_t g_xH[NN*128],  g_xL[NN*128];   // [N][128u]

// ---------------- bf16 split helpers ----------------------------------------
__device__ __forceinline__ uint32_t bf16bits_hi(float x) {
    uint32_t u = __float_as_uint(x);
    return (u + 0x7FFFu + ((u >> 16) & 1u)) & 0xFFFF0000u;   // float bits of rn(bf16)
}
__device__ __forceinline__ void split2(float x, float y, uint32_t& hi2, uint32_t& lo2) {
    uint32_t hx = bf16bits_hi(x);
    uint32_t hy = bf16bits_hi(y);
    float lx = x - __uint_as_float(hx);
    float ly = y - __uint_as_float(hy);
    hi2 = (hx >> 16) | hy;
    lo2 = (bf16bits_hi(lx) >> 16) | bf16bits_hi(ly);
}
__device__ __forceinline__ float silu_fast(float x) {
    return __fdividef(x, 1.0f + __expf(-x));
}

// ---------------- packed f32x2 helpers (Blackwell, base-family feature) -----
__device__ __forceinline__ uint64_t pack_f32x2(float lo, float hi) {
    uint64_t r;
    asm("mov.b64 %0, {%1, %2};" : "=l"(r) : "f"(lo), "f"(hi));
    return r;
}
__device__ __forceinline__ void unpack_f32x2(uint64_t v, float& lo, float& hi) {
    asm("mov.b64 {%0, %1}, %2;" : "=f"(lo), "=f"(hi) : "l"(v));
}
__device__ __forceinline__ void fma_f32x2(uint64_t& d, uint64_t a, uint64_t b) {
    asm("fma.rn.f32x2 %0, %1, %2, %0;" : "+l"(d) : "l"(a), "l"(b));
}

__device__ __forceinline__ uint32_t smem_u32(const void* p) {
    uint32_t a;
    asm("{ .reg .u64 t; cvta.to.shared.u64 t, %1; cvt.u32.u64 %0, t; }"
        : "=r"(a) : "l"(p));
    return a;
}
__device__ __forceinline__ void cp_async16(uint32_t dst, const void* src, int srcBytes) {
    asm volatile("cp.async.cg.shared.global [%0], [%1], 16, %2;"
                 :: "r"(dst), "l"(src), "r"(srcBytes) : "memory");
}
__device__ __forceinline__ void cp_commit() {
    asm volatile("cp.async.commit_group;" ::: "memory");
}
// m16n8k16 bf16 MMA: a = {a0,a1,a2,a3}, b = {b0,b1}
__device__ __forceinline__ void mma_bf16_k16(float* c, const uint32_t* a, const uint32_t* b) {
    asm volatile(
        "mma.sync.aligned.m16n8k16.row.col.f32.bf16.bf16.f32 "
        "{%0,%1,%2,%3}, {%4,%5,%6,%7}, {%8,%9}, {%0,%1,%2,%3};"
        : "+f"(c[0]), "+f"(c[1]), "+f"(c[2]), "+f"(c[3])
        : "r"(a[0]), "r"(a[1]), "r"(a[2]), "r"(a[3]), "r"(b[0]), "r"(b[1]));
}

// ================= bf16x3 mma.sync GEMM (k16, templated tile height) ========
// Rows per CTA = MT*32 (MT=2 -> 64, MT=4 -> 128). N mult of 64, K mult of 32.
// C[M,N] = act(A[M,K] @ BT[N,K]^T + bias). A,B packed split bf16.
#define GBN 64
#define USTR 20
#define BTSg (64*USTR)           /* 1280u per B matrix */

template<int MT>
__global__ __launch_bounds__(256) void gemm_bf16_kernel(
    const uint32_t* __restrict__ AH, const uint32_t* __restrict__ AL,
    const uint32_t* __restrict__ BH, const uint32_t* __restrict__ BL,
    const float* __restrict__ bias, float* __restrict__ Cf,
    uint32_t* __restrict__ CH, uint32_t* __restrict__ CL,
    int M, int K, int N, int act)
{
    constexpr int ROWS = MT * 32;
    constexpr int ATS  = ROWS * USTR;           // uints per A matrix (hi or lo)
    constexpr int STGU = 2*ATS + 2*BTSg;        // one stage
    extern __shared__ __align__(16) uint32_t sm[];
    uint32_t sb = smem_u32(sm);
    int tid  = threadIdx.x;
    int lane = tid & 31;
    int warp = tid >> 5;
    int wm = warp & 1;                  // 2 warps along M (ROWS/2 each)
    int wn = warp >> 1;                 // 4 warps along N (16 cols each)
    int g  = lane >> 2;
    int t  = lane & 3;
    int rowBase = blockIdx.y * ROWS;
    int colBase = blockIdx.x * GBN;
    int K2 = K >> 1;

    int lrow = tid >> 2;                // 0..63
    int lq   = tid & 3;                 // float4 slot (4 uints)

    float acc[MT][2][4];
    #pragma unroll
    for (int mt = 0; mt < MT; mt++)
        #pragma unroll
        for (int nt = 0; nt < 2; nt++)
            #pragma unroll
            for (int q = 0; q < 4; q++) acc[mt][nt][q] = 0.0f;

    int chunks = K >> 5;

    auto loadChunk = [&](int c) {
        if (c < chunks) {
            int s = c & 1;
            int k0u = c << 4;
            uint32_t base = sb + (uint32_t)(s * STGU) * 4u;
            #pragma unroll
            for (int it = 0; it < MT/2; it++) {
                int r = lrow + it * 64;
                int gr = rowBase + r;
                int ok = (gr < M);
                size_t off = (size_t)(ok ? gr : 0) * K2 + k0u + lq * 4;
                uint32_t dr = base + (uint32_t)(r * USTR + lq * 4) * 4u;
                cp_async16(dr, &AH[off], ok ? 16 : 0);
                cp_async16(dr + (uint32_t)ATS * 4u, &AL[off], ok ? 16 : 0);
            }
            size_t boff = (size_t)(colBase + lrow) * K2 + k0u + lq * 4;
            uint32_t db = base + (uint32_t)(2*ATS + lrow * USTR + lq * 4) * 4u;
            cp_async16(db, &BH[boff], 16);
            cp_async16(db + (uint32_t)BTSg * 4u, &BL[boff], 16);
        }
        cp_commit();
    };

    loadChunk(0);
    loadChunk(1);

    for (int c = 0; c < chunks; c++) {
        asm volatile("cp.async.wait_group 1;" ::: "memory");
        __syncthreads();

        const uint32_t* st = sm + (c & 1) * STGU;
        #pragma unroll
        for (int ks = 0; ks < 2; ks++) {                 // two k16 steps per chunk
            uint32_t bHf[2][2], bLf[2][2];
            #pragma unroll
            for (int nt = 0; nt < 2; nt++) {
                int uo = 2*ATS + (wn*16 + nt*8 + g) * USTR + ks*8 + t;
                bHf[nt][0] = st[uo];
                bHf[nt][1] = st[uo + 4];
                bLf[nt][0] = st[BTSg + uo];
                bLf[nt][1] = st[BTSg + uo + 4];
            }
            #pragma unroll
            for (int mt = 0; mt < MT; mt++) {
                uint32_t aHf[4], aLf[4];
                int uo = (wm*(ROWS/2) + mt*16 + g) * USTR + ks*8 + t;
                aHf[0] = st[uo];
                aHf[1] = st[uo + 8*USTR];
                aHf[2] = st[uo + 4];
                aHf[3] = st[uo + 4 + 8*USTR];
                aLf[0] = st[ATS + uo];
                aLf[1] = st[ATS + uo + 8*USTR];
                aLf[2] = st[ATS + uo + 4];
                aLf[3] = st[ATS + uo + 4 + 8*USTR];
                #pragma unroll
                for (int nt = 0; nt < 2; nt++) {
                    mma_bf16_k16(acc[mt][nt], aHf, bHf[nt]);
                    mma_bf16_k16(acc[mt][nt], aHf, bLf[nt]);
                    mma_bf16_k16(acc[mt][nt], aLf, bHf[nt]);
                }
            }
        }
        __syncthreads();
        loadChunk(c + 2);
    }

    // ---- epilogue ----
    int N2 = N >> 1;
    #pragma unroll
    for (int mt = 0; mt < MT; mt++) {
        int r0 = rowBase + wm*(ROWS/2) + mt*16 + g;
        int r1 = r0 + 8;
        #pragma unroll
        for (int nt = 0; nt < 2; nt++) {
            int cc = colBase + wn*16 + nt*8 + t*2;
            float b0 = 0.f, b1 = 0.f;
            if (bias) { b0 = bias[cc]; b1 = bias[cc+1]; }
            float o0 = acc[mt][nt][0] + b0;
            float o1 = acc[mt][nt][1] + b1;
            float o2 = acc[mt][nt][2] + b0;
            float o3 = acc[mt][nt][3] + b1;
            if (act == 1) {
                o0 = silu_fast(o0);
                o1 = silu_fast(o1);
                o2 = silu_fast(o2);
                o3 = silu_fast(o3);
            }
            if (CH) {
                uint32_t h, l;
                if (r0 < M) {
                    split2(o0, o1, h, l);
                    CH[(size_t)r0*N2 + (cc>>1)] = h;
                    CL[(size_t)r0*N2 + (cc>>1)] = l;
                }
                if (r1 < M) {
                    split2(o2, o3, h, l);
                    CH[(size_t)r1*N2 + (cc>>1)] = h;
                    CL[(size_t)r1*N2 + (cc>>1)] = l;
                }
            } else {
                if (r0 < M) *(float2*)&Cf[(size_t)r0*N + cc] = make_float2(o0, o1);
                if (r1 < M) *(float2*)&Cf[(size_t)r1*N + cc] = make_float2(o2, o3);
            }
        }
    }
}

#define SM_BYTES_MT2 ((2*(2*(64*USTR) + 2*BTSg))*4)    /* 40960  */
#define SM_BYTES_MT4 ((2*(2*(128*USTR) + 2*BTSg))*4)   /* 61440  */

// ================= graph-structure + elementwise kernels =====================
__global__ void zero_counts_kernel() {
    int i = blockIdx.x * blockDim.x + threadIdx.x;
    if (i < NN) { g_deg[i] = 0; g_fill[i] = 0; }
}

__global__ void edge_pre_kernel(const float* __restrict__ pos,
                                const int* __restrict__ idx_i,
                                const int* __restrict__ idx_j) {
    int e = blockIdx.x * blockDim.x + threadIdx.x;
    if (e >= EE) return;
    int i = idx_i[e], j = idx_j[e];
    float rx = pos[j*3+0] - pos[i*3+0];
    float ry = pos[j*3+1] - pos[i*3+1];
    float rz = pos[j*3+2] - pos[i*3+2];
    float sq = rx*rx + ry*ry + rz*rz;
    float d  = sqrtf(sq);
    float inv = 1.0f / d;
    g_dir[e*3+0] = rx*inv;
    g_dir[e*3+1] = ry*inv;
    g_dir[e*3+2] = rz*inv;
    int ins = (d < CUT_D) ? 1 : 0;
    float base = (float)M_PI * d / CUT_D;
    float s1, c1;
    sincosf(base, &s1, &c1);
    float cut = ins ? 0.5f * (c1 + 1.0f) : 0.0f;
    g_cut[e] = cut;
    g_inside[e] = ins;
    float ic = inv * cut;
    float twoc = 2.0f * c1;
    float sk = s1, skm1 = 0.0f;
    #pragma unroll
    for (int k = 0; k < RR; k++) {
        g_rbfc[e*RR+k] = sk * ic;
        float nxt = twoc * sk - skm1;
        skm1 = sk; sk = nxt;
    }
    if (ins) atomicAdd(&g_deg[i], 1);
}

// warp-shuffle single-block scan (1024 threads, 32 warps)
__global__ void scan_kernel() {
    __shared__ int wsum[32];
    __shared__ int carry;
    int tid = threadIdx.x, lane = tid & 31, wid = tid >> 5;
    if (tid == 0) { carry = 0; g_rowptr[0] = 0; }
    __syncthreads();
    for (int base = 0; base < NN; base += 1024) {
        int i = base + tid;
        int x = (i < NN) ? g_deg[i] : 0;
        #pragma unroll
        for (int off = 1; off < 32; off <<= 1) {
            int y = __shfl_up_sync(0xFFFFFFFFu, x, off);
            if (lane >= off) x += y;
        }
        if (lane == 31) wsum[wid] = x;
        __syncthreads();
        if (wid == 0) {
            int s = wsum[lane];
            #pragma unroll
            for (int off = 1; off < 32; off <<= 1) {
                int y = __shfl_up_sync(0xFFFFFFFFu, s, off);
                if (lane >= off) s += y;
            }
            wsum[lane] = s;
        }
        __syncthreads();
        int pre = (wid > 0) ? wsum[wid - 1] : 0;
        int inc = x + pre + carry;
        if (i < NN) g_rowptr[i + 1] = inc;
        __syncthreads();
        if (tid == 1023) carry = inc;
        __syncthreads();
    }
}

__global__ void scatter_kernel(const int* __restrict__ idx_i) {
    int e = blockIdx.x * blockDim.x + threadIdx.x;
    if (e >= EE) return;
    if (!g_inside[e]) return;
    int i = idx_i[e];
    int p = g_rowptr[i] + atomicAdd(&g_fill[i], 1);
    g_csr[p] = e;
}

__global__ void init_kernel(const int* __restrict__ z, const float* __restrict__ emb) {
    int idx = blockIdx.x * blockDim.x + threadIdx.x;
    if (idx >= NN*64) return;
    int n = idx >> 6, fq = idx & 63;
    int f0 = fq * 2;
    int zi = z[n];
    float e0 = emb[zi*FF + f0];
    float e1 = emb[zi*FF + f0 + 1];
    g_sA[n*FF + f0]     = e0;
    g_sA[n*FF + f0 + 1] = e1;
    uint32_t h, l;
    split2(e0, e1, h, l);
    g_sH[idx] = h; g_sL[idx] = l;
    size_t vb = (size_t)n * F3 + f0;
    g_vA[vb] = 0.f;        g_vA[vb+1] = 0.f;
    g_vA[vb+FF] = 0.f;     g_vA[vb+FF+1] = 0.f;
    g_vA[vb+2*FF] = 0.f;   g_vA[vb+2*FF+1] = 0.f;
}

// transpose-pack ALL weights into split bf16 [N][K/2 uints] per matrix, per layer
__global__ void pack_w_kernel(const float* __restrict__ w1, const float* __restrict__ w2,
                              const float* __restrict__ U,  const float* __restrict__ V,
                              const float* __restrict__ u1, const float* __restrict__ u2) {
    int idx = blockIdx.x * blockDim.x + threadIdx.x;
    if (idx >= LL*PSu) return;
    int l = idx / PSu, r = idx % PSu;
    float v0, v1;
    if (r < OW2u) {                    // w1T [128][64u]
        int n = r >> 6, k0 = (r & 63) * 2;
        v0 = w1[(size_t)l*16384 + k0*128 + n];
        v1 = w1[(size_t)l*16384 + (k0+1)*128 + n];
    } else if (r < OUVu) {             // w2T [384][64u]
        int r2 = r - OW2u; int n = r2 >> 6, k0 = (r2 & 63) * 2;
        v0 = w2[(size_t)l*49152 + k0*384 + n];
        v1 = w2[(size_t)l*49152 + (k0+1)*384 + n];
    } else if (r < OU1u) {             // UVwT [256][64u] = U|V cols
        int r2 = r - OUVu; int n = r2 >> 6, k0 = (r2 & 63) * 2;
        if (n < 128) {
            v0 = U[(size_t)l*16384 + k0*128 + n];
            v1 = U[(size_t)l*16384 + (k0+1)*128 + n];
        } else {
            v0 = V[(size_t)l*16384 + k0*128 + (n-128)];
            v1 = V[(size_t)l*16384 + (k0+1)*128 + (n-128)];
        }
    } else if (r < OU2u) {             // u1T [128][128u]
        int r2 = r - OU1u; int n = r2 >> 7, k0 = (r2 & 127) * 2;
        v0 = u1[(size_t)l*32768 + k0*128 + n];
        v1 = u1[(size_t)l*32768 + (k0+1)*128 + n];
    } else {                           // u2T [384][64u]
        int r2 = r - OU2u; int n = r2 >> 6, k0 = (r2 & 63) * 2;
        v0 = u2[(size_t)l*49152 + k0*384 + n];
        v1 = u2[(size_t)l*49152 + (k0+1)*384 + n];
    }
    uint32_t h, l2;
    split2(v0, v1, h, l2);
    g_wH[idx] = h; g_wL[idx] = l2;
}

// ---------------- fused message kernel (f32x2 RBF, split vOut) --------------
// vz != 0: vIn is identically zero (layer 0) -> skip the vIn gathers.
__global__ __launch_bounds__(128) void msg_kernel(
    const float* __restrict__ sIn, const float* __restrict__ vIn,
    const float* __restrict__ phi,
    float* __restrict__ sOut, float* __restrict__ vOut,
    const int* __restrict__ idx_j,
    const float* __restrict__ rbw, const float* __restrict__ rbb, int vz)
{
    int f = threadIdx.x;
    // packed weight pairs: (w[2k], w[2k+1]) per chain
    uint64_t w2v[RR/2], w2s[RR/2], w2q[RR/2];
    #pragma unroll
    for (int k = 0; k < RR/2; k++) {
        w2v[k] = pack_f32x2(rbw[(2*k)*F3 + f],        rbw[(2*k+1)*F3 + f]);
        w2s[k] = pack_f32x2(rbw[(2*k)*F3 + FF + f],   rbw[(2*k+1)*F3 + FF + f]);
        w2q[k] = pack_f32x2(rbw[(2*k)*F3 + 2*FF + f], rbw[(2*k+1)*F3 + 2*FF + f]);
    }
    float bvv = rbb[f], bss = rbb[FF+f], bvs = rbb[2*FF+f];
    const uint64_t zero2 = pack_f32x2(0.0f, 0.0f);

    int i = blockIdx.x;
    int p0 = g_rowptr[i], p1 = g_rowptr[i+1];
    float accs = 0.f, av0 = 0.f, av1 = 0.f, av2 = 0.f;
    for (int p = p0; p < p1; p++) {
        int e = g_csr[p];
        int j = idx_j[e];
        float cut = g_cut[e];
        float d0 = g_dir[e*3+0], d1 = g_dir[e*3+1], d2 = g_dir[e*3+2];
        // rbfc row: 20 floats = 5 float4 (16B-aligned: e*80 bytes)
        const float4* rc4 = (const float4*)&g_rbfc[(size_t)e * RR];
        float4 r0 = rc4[0], r1 = rc4[1], r2 = rc4[2], r3 = rc4[3], r4 = rc4[4];
        uint64_t rp[RR/2];
        rp[0] = pack_f32x2(r0.x, r0.y); rp[1] = pack_f32x2(r0.z, r0.w);
        rp[2] = pack_f32x2(r1.x, r1.y); rp[3] = pack_f32x2(r1.z, r1.w);
        rp[4] = pack_f32x2(r2.x, r2.y); rp[5] = pack_f32x2(r2.z, r2.w);
        rp[6] = pack_f32x2(r3.x, r3.y); rp[7] = pack_f32x2(r3.z, r3.w);
        rp[8] = pack_f32x2(r4.x, r4.y); rp[9] = pack_f32x2(r4.z, r4.w);
        uint64_t av = zero2, as_ = zero2, aq = zero2;
        #pragma unroll
        for (int k = 0; k < RR/2; k++) {
            fma_f32x2(av,  rp[k], w2v[k]);
            fma_f32x2(as_, rp[k], w2s[k]);
            fma_f32x2(aq,  rp[k], w2q[k]);
        }
        float vlo, vhi, slo, shi, qlo, qhi;
        unpack_f32x2(av,  vlo, vhi);
        unpack_f32x2(as_, slo, shi);
        unpack_f32x2(aq,  qlo, qhi);
        float Wv = vlo + vhi + bvv*cut;
        float Ws = slo + shi + bss*cut;
        float Wq = qlo + qhi + bvs*cut;

        const float* ph = &phi[(size_t)j * F3];
        float pvv = ph[f]        * Wv;
        float pss = ph[FF + f]   * Ws;
        float pvs = ph[2*FF + f] * Wq;
        accs += pss;
        if (vz) {
            av0 += pvs * d0;
            av1 += pvs * d1;
            av2 += pvs * d2;
        } else {
            const float* vj = &vIn[(size_t)j * F3];
            av0 += vj[f]        * pvv + pvs * d0;
            av1 += vj[FF + f]   * pvv + pvs * d1;
            av2 += vj[2*FF + f] * pvv + pvs * d2;
        }
    }
    sOut[(size_t)i*FF + f] = sIn[(size_t)i*FF + f] + accs;
    size_t vb = (size_t)i * F3;
    float n0, n1, n2;
    if (vz) { n0 = av0; n1 = av1; n2 = av2; }
    else {
        n0 = vIn[vb + f]        + av0;
        n1 = vIn[vb + FF + f]   + av1;
        n2 = vIn[vb + 2*FF + f] + av2;
    }
    vOut[vb + f]        = n0;
    vOut[vb + FF + f]   = n1;
    vOut[vb + 2*FF + f] = n2;
    // split pairs for the UV GEMM
    float q0 = __shfl_down_sync(0xFFFFFFFFu, n0, 1);
    float q1 = __shfl_down_sync(0xFFFFFFFFu, n1, 1);
    float q2 = __shfl_down_sync(0xFFFFFFFFu, n2, 1);
    if ((f & 1) == 0) {
        size_t rb = (size_t)i * 192 + (f >> 1);
        uint32_t h, l;
        split2(n0, q0, h, l); g_vH[rb]       = h; g_vL[rb]       = l;
        split2(n1, q1, h, l); g_vH[rb + 64]  = h; g_vL[rb + 64]  = l;
        split2(n2, q2, h, l); g_vH[rb + 128] = h; g_vL[rb + 128] = l;
    }
}

// ---------------- x = concat(safe_norm(Vv), sfeat) -> split only ------------
__global__ void buildx_kernel(const float* __restrict__ s) {
    int idx = blockIdx.x * blockDim.x + threadIdx.x;
    if (idx >= NN*128) return;
    int n = idx >> 7, cq = idx & 127;
    int c0 = cq * 2;
    float x0, x1;
    if (c0 < FF) {
        size_t b = (size_t)n * 768 + 128 + c0;
        float v0 = g_UVv[b],   v1 = g_UVv[b + 256],   v2 = g_UVv[b + 512];
        float u0 = g_UVv[b+1], u1 = g_UVv[b + 257],   u2 = g_UVv[b + 513];
        float sq0 = v0*v0 + v1*v1 + v2*v2;
        float sq1 = u0*u0 + u1*u1 + u2*u2;
        x0 = (sq0 > 0.0f) ? sqrtf(sq0) : 0.0f;
        x1 = (sq1 > 0.0f) ? sqrtf(sq1) : 0.0f;
    } else {
        x0 = s[(size_t)n*FF + (c0 - FF)];
        x1 = s[(size_t)n*FF + (c0 - FF) + 1];
    }
    uint32_t h, l;
    split2(x0, x1, h, l);
    g_xH[idx] = h; g_xL[idx] = l;
}

// ---------------- update block (also emits split s) -------------------------
__global__ void update_kernel(float* __restrict__ s, float* __restrict__ v) {
    int idx = blockIdx.x * blockDim.x + threadIdx.x;
    if (idx >= NN*64) return;
    int n = idx >> 6, fq = idx & 63;
    int f0 = fq * 2, f1 = f0 + 1;
    size_t ub = (size_t)n * 768;
    float u00 = g_UVv[ub+f0], u01 = g_UVv[ub+256+f0], u02 = g_UVv[ub+512+f0];
    float u10 = g_UVv[ub+f1], u11 = g_UVv[ub+256+f1], u12 = g_UVv[ub+512+f1];
    float w00 = g_UVv[ub+128+f0], w01 = g_UVv[ub+384+f0], w02 = g_UVv[ub+640+f0];
    float w10 = g_UVv[ub+128+f1], w11 = g_UVv[ub+384+f1], w12 = g_UVv[ub+640+f1];
    float dot0 = u00*w00 + u01*w01 + u02*w02;
    float dot1 = u10*w10 + u11*w11 + u12*w12;
    const float* an = &g_a[(size_t)n * F3];
    float avv0 = an[f0], asv0 = an[FF+f0], ass0 = an[2*FF+f0];
    float avv1 = an[f1], asv1 = an[FF+f1], ass1 = an[2*FF+f1];
    size_t b = (size_t)n * F3 + f0;
    v[b]          += u00 * avv0;
    v[b + 1]      += u10 * avv1;
    v[b + FF]     += u01 * avv0;
    v[b + FF + 1] += u11 * avv1;
    v[b + 2*FF]     += u02 * avv0;
    v[b + 2*FF + 1] += u12 * avv1;
    float s0 = s[(size_t)n*FF + f0] + ass0 + asv0 * dot0;
    float s1 = s[(size_t)n*FF + f1] + ass1 + asv1 * dot1;
    s[(size_t)n*FF + f0] = s0;
    s[(size_t)n*FF + f1] = s1;
    uint32_t h, l;
    split2(s0, s1, h, l);
    g_sH[idx] = h; g_sL[idx] = l;
}

__global__ void output_kernel(const float* __restrict__ s, const float* __restrict__ v,
                              float* __restrict__ out) {
    int idx = blockIdx.x * blockDim.x + threadIdx.x;
    if (idx >= NN*FF) return;
    int n = idx / FF, f = idx % FF;
    out[idx] = s[idx];
    size_t ob = (size_t)NN*FF + (size_t)idx * 3;
    size_t vb = (size_t)n * F3 + f;
    out[ob + 0] = v[vb];
    out[ob + 1] = v[vb + FF];
    out[ob + 2] = v[vb + 2*FF];
}

// ---------------- host orchestration ----------------------------------------
static inline void launch_gemm64(const uint32_t* AH, const uint32_t* AL,
                                 const uint32_t* BH, const uint32_t* BL,
                                 const float* bias, float* Cf,
                                 uint32_t* CH, uint32_t* CL,
                                 int M, int K, int N, int act) {
    dim3 grid(N / GBN, (M + 63) / 64);
    gemm_bf16_kernel<2><<<grid, 256, SM_BYTES_MT2>>>(AH, AL, BH, BL, bias, Cf, CH, CL, M, K, N, act);
}
static inline void launch_gemm128(const uint32_t* AH, const uint32_t* AL,
                                  const uint32_t* BH, const uint32_t* BL,
                                  const float* bias, float* Cf,
                                  uint32_t* CH, uint32_t* CL,
                                  int M, int K, int N, int act) {
    dim3 grid(N / GBN, (M + 127) / 128);
    gemm_bf16_kernel<4><<<grid, 256, SM_BYTES_MT4>>>(AH, AL, BH, BL, bias, Cf, CH, CL, M, K, N, act);
}

extern "C" void kernel_launch(void* const* d_in, const int* in_sizes, int n_in,
                              void* d_out, int out_size) {
    const int*   z      = (const int*)  d_in[0];
    const float* pos    = (const float*)d_in[1];
    const int*   idx_i  = (const int*)  d_in[2];
    const int*   idx_j  = (const int*)  d_in[3];
    const float* emb    = (const float*)d_in[4];
    const float* msg_w1 = (const float*)d_in[5];
    const float* msg_b1 = (const float*)d_in[6];
    const float* msg_w2 = (const float*)d_in[7];
    const float* msg_b2 = (const float*)d_in[8];
    const float* rbf_w  = (const float*)d_in[9];
    const float* rbf_b  = (const float*)d_in[10];
    const float* upd_U  = (const float*)d_in[11];
    const float* upd_V  = (const float*)d_in[12];
    const float* upd_w1 = (const float*)d_in[13];
    const float* upd_b1 = (const float*)d_in[14];
    const float* upd_w2 = (const float*)d_in[15];
    const float* upd_b2 = (const float*)d_in[16];
    float* out = (float*)d_out;

    cudaFuncSetAttribute(gemm_bf16_kernel<2>,
                         cudaFuncAttributeMaxDynamicSharedMemorySize, SM_BYTES_MT2);
    cudaFuncSetAttribute(gemm_bf16_kernel<4>,
                         cudaFuncAttributeMaxDynamicSharedMemorySize, SM_BYTES_MT4);

    float *sA, *sB, *vA, *vB, *phi, *UVv, *aa;
    cudaGetSymbolAddress((void**)&sA,  g_sA);
    cudaGetSymbolAddress((void**)&sB,  g_sB);
    cudaGetSymbolAddress((void**)&vA,  g_vA);
    cudaGetSymbolAddress((void**)&vB,  g_vB);
    cudaGetSymbolAddress((void**)&phi, g_phi);
    cudaGetSymbolAddress((void**)&UVv, g_UVv);
    cudaGetSymbolAddress((void**)&aa,  g_a);
    uint32_t *wH, *wL, *sH, *sL, *hidH, *hidL, *vH, *vL, *xH, *xL;
    cudaGetSymbolAddress((void**)&wH,   g_wH);
    cudaGetSymbolAddress((void**)&wL,   g_wL);
    cudaGetSymbolAddress((void**)&sH,   g_sH);
    cudaGetSymbolAddress((void**)&sL,   g_sL);
    cudaGetSymbolAddress((void**)&hidH, g_hidH);
    cudaGetSymbolAddress((void**)&hidL, g_hidL);
    cudaGetSymbolAddress((void**)&vH,   g_vH);
    cudaGetSymbolAddress((void**)&vL,   g_vL);
    cudaGetSymbolAddress((void**)&xH,   g_xH);
    cudaGetSymbolAddress((void**)&xL,   g_xL);

    // ---- setup (replayed each graph iteration; deterministic) ----
    pack_w_kernel<<<(LL*PSu + 255)/256, 256>>>(msg_w1, msg_w2, upd_U, upd_V, upd_w1, upd_w2);
    init_kernel<<<(NN*64 + 255)/256, 256>>>(z, emb);
    zero_counts_kernel<<<(NN + 255)/256, 256>>>();

    float* sCur = sA; float* sNxt = sB;
    float* vCur = vA; float* vNxt = vB;

    for (int l = 0; l < 3; l++) {
        const uint32_t* lwH = wH + (size_t)l * PSu;
        const uint32_t* lwL = wL + (size_t)l * PSu;
        // hid = silu(s @ w1 + b1)  [split out]  M=10000, N=128 -> 64-row tiles
        launch_gemm64(sH, sL, lwH + OW1u, lwL + OW1u, msg_b1 + (size_t)l*FF,
                      nullptr, hidH, hidL, NN, 128, 128, 1);
        if (l == 0) {
            edge_pre_kernel<<<(EE + 255)/256, 256>>>(pos, idx_i, idx_j);
            scan_kernel<<<1, 1024>>>();
            scatter_kernel<<<(EE + 255)/256, 256>>>(idx_i);
        }
        // phi = hid @ w2 + b2  [fp32 out]
        launch_gemm128(hidH, hidL, lwH + OW2u, lwL + OW2u, msg_b2 + (size_t)l*F3,
                       phi, nullptr, nullptr, NN, 128, 384, 0);
        // message pass (writes fp32 + split v); one node per block
        msg_kernel<<<NN, 128>>>(sCur, vCur, phi, sNxt, vNxt, idx_j,
                                rbf_w + (size_t)l*RR*F3, rbf_b + (size_t)l*F3,
                                (l == 0) ? 1 : 0);
        // [Uv | Vv] = vNxt[3N,F] @ UVw[F,2F]  [fp32 out]
        launch_gemm128(vH, vL, lwH + OUVu, lwL + OUVu, nullptr,
                       UVv, nullptr, nullptr, 3*NN, 128, 256, 0);
        // x = concat(||Vv||, s) -> split only
        buildx_kernel<<<(NN*128 + 255)/256, 256>>>(sNxt);
        // hid = silu(x @ uw1 + ub1)  [split out]  M=10000, N=128 -> 64-row tiles
        launch_gemm64(xH, xL, lwH + OU1u, lwL + OU1u, upd_b1 + (size_t)l*FF,
                      nullptr, hidH, hidL, NN, 256, 128, 1);
        // a = hid @ uw2 + ub2  [fp32 out]
        launch_gemm128(hidH, hidL, lwH + OU2u, lwL + OU2u, upd_b2 + (size_t)l*F3,
                       aa, nullptr, nullptr, NN, 128, 384, 0);
        // in-place update (also refreshes split s)
        update_kernel<<<(NN*64 + 255)/256, 256>>>(sNxt, vNxt);

        float* t;
        t = sCur; sCur = sNxt; sNxt = t;
        t = vCur; vCur = vNxt; vNxt = t;
    }

    output_kernel<<<(NN*FF + 255)/256, 256>>>(sCur, vCur, out);
}